// round 13
// baseline (speedup 1.0000x reference)
#include <cuda_runtime.h>
#include <math_constants.h>

#define KVOL 27
#define C4   24                 // 96 channels = 24 float4
#define RPB  16                 // rows per block-iteration: 24*16 = 384 threads
#define NSM  148
#define BLKS_PER_SM 4

// L2 policy: keep in_feat lines resident (evict-last priority).
__device__ __forceinline__ unsigned long long mk_keep_policy() {
    unsigned long long pol;
    asm("createpolicy.fractional.L2::evict_last.b64 %0, 1.0;" : "=l"(pol));
    return pol;
}

// Gather load: bypass L1 (.cg) + evict_last L2 policy.
__device__ __forceinline__ float4 ldg_gather(const float4* p, unsigned long long pol) {
    float4 v;
    asm("ld.global.cg.L2::cache_hint.v4.f32 {%0,%1,%2,%3}, [%4], %5;"
        : "=f"(v.x), "=f"(v.y), "=f"(v.z), "=f"(v.w) : "l"(p), "l"(pol));
    return v;
}

__device__ __forceinline__ void vmax(float4& m, const float4 v) {
    m.x = fmaxf(m.x, v.x);
    m.y = fmaxf(m.y, v.y);
    m.z = fmaxf(m.z, v.z);
    m.w = fmaxf(m.w, v.w);
}

// Gather B neighbors with all B loads in flight, then reduce.
template <int B, typename IDX>
__device__ __forceinline__ void gather_batch(const float4* __restrict__ feat,
                                             const IDX* __restrict__ nm, int kb,
                                             float4& m, unsigned long long pol) {
    unsigned idx[B];
    #pragma unroll
    for (int j = 0; j < B; ++j)
        idx[j] = (unsigned)__ldcs(&nm[kb + j]);        // streaming index read
    float4 v[B];
    #pragma unroll
    for (int j = 0; j < B; ++j)                        // B x 16B outstanding
        v[j] = ldg_gather(feat + (size_t)idx[j] * C4, pol);
    #pragma unroll
    for (int j = 0; j < B; ++j)
        vmax(m, v[j]);
}

template <typename IDX>
__device__ __forceinline__ void pool_row(const float4* __restrict__ feat,
                                         const IDX* __restrict__ nm,
                                         float4* __restrict__ outp,
                                         unsigned long long pol) {
    float4 m = make_float4(-CUDART_INF_F, -CUDART_INF_F, -CUDART_INF_F, -CUDART_INF_F);
    gather_batch<7>(feat, nm, 0,  m, pol);             // converged geometry:
    gather_batch<7>(feat, nm, 7,  m, pol);             // ~330 sectors/SM
    gather_batch<7>(feat, nm, 14, m, pol);             // outstanding
    gather_batch<6>(feat, nm, 21, m, pol);
    __stcs(outp, m);                                   // streaming store
}

// Persistent single-wave kernel: 592 blocks (148 SM x 4), grid-stride over
// rows. Removes ~10 wave transitions and runs the dtype preamble 592x
// instead of 6250x; the row loop keeps the gather pipeline primed.
__global__ __launch_bounds__(C4 * RPB, BLKS_PER_SM)
void sparse_maxpool_kernel(const float4* __restrict__ in_feat,
                           const void* __restrict__ nmap,
                           float4* __restrict__ out,
                           int n_out, int n_in_rows) {
    // ---- Inline dtype detection (once per persistent block; L2-hot) ----
    __shared__ int s_bad;
    int t = threadIdx.y * C4 + threadIdx.x;
    if (t == 0) s_bad = 0;
    __syncthreads();
    if (t < 64) {
        const long long* p = (const long long*)nmap;
        long long v = p[t];
        if (v < 0 || v >= (long long)n_in_rows) atomicOr(&s_bad, 1);
    }
    __syncthreads();
    int is64 = (s_bad == 0);

    const unsigned long long pol = mk_keep_policy();
    int c4 = threadIdx.x;                              // 0..23
    const float4* feat_c = in_feat + c4;
    const int stride = gridDim.x * RPB;

    if (is64) {
        const long long* nmb = (const long long*)nmap;
        for (int row = blockIdx.x * RPB + threadIdx.y; row < n_out; row += stride)
            pool_row(feat_c, nmb + (size_t)row * KVOL,
                     out + (size_t)row * C4 + c4, pol);
    } else {
        const int* nmb = (const int*)nmap;
        for (int row = blockIdx.x * RPB + threadIdx.y; row < n_out; row += stride)
            pool_row(feat_c, nmb + (size_t)row * KVOL,
                     out + (size_t)row * C4 + c4, pol);
    }
}

extern "C" void kernel_launch(void* const* d_in, const int* in_sizes, int n_in,
                              void* d_out, int out_size) {
    const float4* in_feat = (const float4*)d_in[0];
    const void*   nmap    = (const void*)d_in[1];
    float4*       out     = (float4*)d_out;

    int nmap_elems = in_sizes[1];                      // N_OUT * KVOL
    int n_out      = nmap_elems / KVOL;                // 100000
    int n_in_rows  = in_sizes[0] / 96;                 // 400000

    dim3 block(C4, RPB);
    int grid = NSM * BLKS_PER_SM;                      // single persistent wave
    int max_grid = (n_out + RPB - 1) / RPB;
    if (grid > max_grid) grid = max_grid;
    sparse_maxpool_kernel<<<grid, block>>>(in_feat, nmap, out, n_out, n_in_rows);
}

// round 14
// speedup vs baseline: 1.0221x; 1.0221x over previous
#include <cuda_runtime.h>
#include <math_constants.h>

#define KVOL 27
#define C4   24                 // 96 channels = 24 float4
#define RPB  16                 // rows per block: 24*16 = 384 threads
#define NTHREADS (C4 * RPB)

// L2 policy: keep in_feat lines resident (evict-last priority).
__device__ __forceinline__ unsigned long long mk_keep_policy() {
    unsigned long long pol;
    asm("createpolicy.fractional.L2::evict_last.b64 %0, 1.0;" : "=l"(pol));
    return pol;
}

// Gather load: bypass L1 (.cg) + evict_last L2 policy.
__device__ __forceinline__ float4 ldg_gather(const float4* p, unsigned long long pol) {
    float4 v;
    asm("ld.global.cg.L2::cache_hint.v4.f32 {%0,%1,%2,%3}, [%4], %5;"
        : "=f"(v.x), "=f"(v.y), "=f"(v.z), "=f"(v.w) : "l"(p), "l"(pol));
    return v;
}

__device__ __forceinline__ void vmax(float4& m, const float4 v) {
    m.x = fmaxf(m.x, v.x);
    m.y = fmaxf(m.y, v.y);
    m.z = fmaxf(m.z, v.z);
    m.w = fmaxf(m.w, v.w);
}

// Gather B neighbors (indices from smem) with all B loads in flight, then reduce.
template <int B>
__device__ __forceinline__ void gather_batch(const float4* __restrict__ feat,
                                             const int* __restrict__ s_idx, int kb,
                                             float4& m, unsigned long long pol) {
    unsigned idx[B];
    #pragma unroll
    for (int j = 0; j < B; ++j)
        idx[j] = (unsigned)s_idx[kb + j];              // LDS broadcast (conflict-free)
    float4 v[B];
    #pragma unroll
    for (int j = 0; j < B; ++j)                        // B x 16B outstanding
        v[j] = ldg_gather(feat + (size_t)idx[j] * C4, pol);
    #pragma unroll
    for (int j = 0; j < B; ++j)
        vmax(m, v[j]);
}

// R11 geometry (36 warps/SM, 9/9/9 batches) + cooperative index staging:
// all 432 block indices loaded coalesced into smem once, freeing the LSU /
// L1tex queue from 27 per-thread scalar index LDGs per row.
__global__ __launch_bounds__(NTHREADS, 3)
void sparse_maxpool_kernel(const float4* __restrict__ in_feat,
                           const void* __restrict__ nmap,
                           float4* __restrict__ out,
                           int n_out, int n_in_rows) {
    __shared__ int s_bad;
    __shared__ int s_idx[RPB][KVOL];                   // 432 ints = 1.7 KB

    int t = threadIdx.y * C4 + threadIdx.x;
    if (t == 0) s_bad = 0;
    __syncthreads();
    if (t < 64) {                                      // dtype probe (512B, L2-hot)
        const long long* p = (const long long*)nmap;
        long long v = p[t];
        if (v < 0 || v >= (long long)n_in_rows) atomicOr(&s_bad, 1);
    }
    __syncthreads();
    int is64 = (s_bad == 0);

    int row0 = blockIdx.x * RPB;
    int nrows = min(RPB, n_out - row0);
    int nelem = nrows * KVOL;

    // ---- Cooperative, coalesced index staging into smem ----
    if (is64) {
        const long long* nmb = (const long long*)nmap + (size_t)row0 * KVOL;
        for (int e = t; e < nelem; e += NTHREADS)
            s_idx[e / KVOL][e % KVOL] = (int)__ldcs(&nmb[e]);
    } else {
        const int* nmb = (const int*)nmap + (size_t)row0 * KVOL;
        for (int e = t; e < nelem; e += NTHREADS)
            s_idx[e / KVOL][e % KVOL] = __ldcs(&nmb[e]);
    }
    __syncthreads();

    int row = row0 + threadIdx.y;
    if (row >= n_out) return;
    int c4 = threadIdx.x;                              // 0..23

    const unsigned long long pol = mk_keep_policy();
    const float4* feat_c = in_feat + c4;
    const int* my_idx = s_idx[threadIdx.y];

    float4 m = make_float4(-CUDART_INF_F, -CUDART_INF_F, -CUDART_INF_F, -CUDART_INF_F);
    gather_batch<9>(feat_c, my_idx, 0,  m, pol);
    gather_batch<9>(feat_c, my_idx, 9,  m, pol);
    gather_batch<9>(feat_c, my_idx, 18, m, pol);
    __stcs(out + (size_t)row * C4 + c4, m);            // streaming store
}

extern "C" void kernel_launch(void* const* d_in, const int* in_sizes, int n_in,
                              void* d_out, int out_size) {
    const float4* in_feat = (const float4*)d_in[0];
    const void*   nmap    = (const void*)d_in[1];
    float4*       out     = (float4*)d_out;

    int nmap_elems = in_sizes[1];                      // N_OUT * KVOL
    int n_out      = nmap_elems / KVOL;                // 100000
    int n_in_rows  = in_sizes[0] / 96;                 // 400000

    dim3 block(C4, RPB);
    int grid = (n_out + RPB - 1) / RPB;
    sparse_maxpool_kernel<<<grid, block>>>(in_feat, nmap, out, n_out, n_in_rows);
}